// round 14
// baseline (speedup 1.0000x reference)
#include <cuda_runtime.h>
#include <cuda_bf16.h>
#include <math.h>
#include <stdint.h>

#define N_SEQ 4096
#define SEQ_S 128
#define T_STEPS 127
#define VOCAB 36
#define E_DIM 128
#define H_DIM 256
#define G_DIM 1024
#define NH (N_SEQ * H_DIM)             // 1048576 elems per h plane
#define IMG_E 4096                      // elems per 128x32 bf16 image (8KB)
#define IMG_B 8192                      // bytes per image
#define STAGE_BYTES 32768               // Ahi/Alo/Bhi/Blo 8KB each
#define NSTAGE 3
#define SMEM_SZ 99456

static const size_t PROBS_OFF = (size_t)N_SEQ * T_STEPS * VOCAB;  // 18726912

// ---------------- device scratch (no allocations allowed) ----------------
__device__ __align__(128) __nv_bfloat16 g_W0hi[8 * 8 * IMG_E],  g_W0lo[8 * 8 * IMG_E];
__device__ __align__(128) __nv_bfloat16 g_W1hi[8 * 16 * IMG_E], g_W1lo[8 * 16 * IMG_E];
__device__ __align__(128) __nv_bfloat16 g_h0hi[2 * NH], g_h0lo[2 * NH];   // swizzled k32 images
__device__ __align__(128) __nv_bfloat16 g_h1hi[2 * NH], g_h1lo[2 * NH];
__device__ __align__(128) float g_h1f[(size_t)T_STEPS * NH];              // fp32 h1 history for fc
__device__ __align__(128) float g_projP[VOCAB * G_DIM];                   // emb@W_ih0^T + b, unit-major
__device__ __align__(128) float g_b1U[G_DIM];
__device__ __align__(128) float g_c0[NH], g_c1[NH];
__device__ float g_acc[N_SEQ], g_len[N_SEQ];

// ---------------- helpers ----------------
__device__ __forceinline__ unsigned smem_u32(const void* p) {
    unsigned a;
    asm("{ .reg .u64 t; cvta.to.shared.u64 t, %1; cvt.u32.u64 %0, t; }" : "=r"(a) : "l"(p));
    return a;
}
// elem offset inside a 128x32 bf16 image, 64B rows, conflict-free ldmatrix swizzle
__device__ __forceinline__ int eoff32(int r, int kk) {
    return r * 32 + ((((kk >> 3) ^ ((r >> 1) & 3)) & 3) << 3) + (kk & 7);
}
__device__ __forceinline__ float fsig(float x) { return __fdividef(1.0f, 1.0f + __expf(-x)); }
__device__ __forceinline__ float ftanh(float x) { return __fdividef(2.0f, 1.0f + __expf(-2.0f * x)) - 1.0f; }

#define MBAR_INIT(addr, cnt) \
    asm volatile("mbarrier.init.shared.b64 [%0], %1;" :: "r"(addr), "r"(cnt) : "memory")
#define MBAR_EXPECT(addr, tx) \
    asm volatile("mbarrier.arrive.expect_tx.shared.b64 _, [%0], %1;" :: "r"(addr), "r"(tx) : "memory")
#define MBAR_ARRIVE(addr) \
    asm volatile("mbarrier.arrive.shared.b64 _, [%0];" :: "r"(addr) : "memory")
#define BULK_G2S(dst, src, bytes, mb) \
    asm volatile("cp.async.bulk.shared::cta.global.mbarrier::complete_tx::bytes [%0], [%1], %2, [%3];" \
                 :: "r"(dst), "l"(src), "r"(bytes), "r"(mb) : "memory")

__device__ __forceinline__ void mbar_wait(unsigned addr, unsigned parity) {
    unsigned done;
    asm volatile("{\n\t.reg .pred p;\n\t"
                 "mbarrier.try_wait.parity.acquire.cta.shared::cta.b64 p, [%1], %2;\n\t"
                 "selp.b32 %0, 1, 0, p;\n\t}" : "=r"(done) : "r"(addr), "r"(parity) : "memory");
    if (!done) {
        asm volatile("{\n\t.reg .pred P1;\n\t"
                     "WL_%=:\n\t"
                     "mbarrier.try_wait.parity.acquire.cta.shared::cta.b64 P1, [%0], %1, 0x989680;\n\t"
                     "@P1 bra.uni WD_%=;\n\t"
                     "bra.uni WL_%=;\n\t"
                     "WD_%=:\n\t}" :: "r"(addr), "r"(parity) : "memory");
    }
}

#define LDSM4(r0, r1, r2, r3, addr) \
    asm volatile("ldmatrix.sync.aligned.m8n8.x4.shared.b16 {%0,%1,%2,%3}, [%4];" \
                 : "=r"(r0), "=r"(r1), "=r"(r2), "=r"(r3) : "r"(addr))

#define MMA16816(d, a, b0, b1) \
    asm volatile("mma.sync.aligned.m16n8k16.row.col.f32.bf16.bf16.f32 " \
                 "{%0,%1,%2,%3}, {%4,%5,%6,%7}, {%8,%9}, {%0,%1,%2,%3};" \
                 : "+f"((d)[0]), "+f"((d)[1]), "+f"((d)[2]), "+f"((d)[3]) \
                 : "r"((a)[0]), "r"((a)[1]), "r"((a)[2]), "r"((a)[3]), "r"(b0), "r"(b1))

// ---------------- prep: permute + split weights into swizzled k32 images ----------------
__device__ __forceinline__ int perm_nloc(int gate, int q, int& blockN) {
    blockN = q >> 5;
    int rem = q & 31, wcol = rem >> 4, rem2 = rem & 15, a = rem2 >> 2, jp = rem2 & 3;
    return wcol * 64 + 2 * a + 16 * jp + 8 * (gate >> 1) + (gate & 1);
}

__global__ void prep_w(const float* __restrict__ W_hh0,
                       const float* __restrict__ W_ih1, const float* __restrict__ W_hh1,
                       const float* __restrict__ b_ih1, const float* __restrict__ b_hh1) {
    int jo = blockIdx.x, tid = threadIdx.x;          // original gate row 0..1023
    int gate = jo >> 8, q = jo & 255;
    int bN;
    int nloc = perm_nloc(gate, q, bN);
    for (int k = tid; k < H_DIM; k += 128) {         // W0 = W_hh0 only (ih0 folded into proj)
        float v = W_hh0[jo * H_DIM + k];
        __nv_bfloat16 hi = __float2bfloat16(v);
        __nv_bfloat16 lo = __float2bfloat16(v - __bfloat162float(hi));
        int idx = (bN * 8 + (k >> 5)) * IMG_E + eoff32(nloc, k & 31);
        g_W0hi[idx] = hi; g_W0lo[idx] = lo;
    }
    for (int k = tid; k < 512; k += 128) {           // W1 = [W_ih1 | W_hh1]
        float v = (k < H_DIM) ? W_ih1[jo * H_DIM + k] : W_hh1[jo * H_DIM + k - H_DIM];
        __nv_bfloat16 hi = __float2bfloat16(v);
        __nv_bfloat16 lo = __float2bfloat16(v - __bfloat162float(hi));
        int idx = (bN * 16 + (k >> 5)) * IMG_E + eoff32(nloc, k & 31);
        g_W1hi[idx] = hi; g_W1lo[idx] = lo;
    }
    if (tid == 0) g_b1U[q * 4 + gate] = b_ih1[jo] + b_hh1[jo];
}

// proj[tok][q*4+gate] = emb[tok] . W_ih0[row] + b_ih0 + b_hh0  (exact fp32)
__global__ void prep_proj(const float* __restrict__ emb, const float* __restrict__ W_ih0,
                          const float* __restrict__ b_ih0, const float* __restrict__ b_hh0) {
    __shared__ float e[E_DIM];
    int tok = blockIdx.x, tid = threadIdx.x;
    if (tid < E_DIM) e[tid] = emb[tok * E_DIM + tid];
    __syncthreads();
    for (int jo = tid; jo < G_DIM; jo += 256) {
        int gate = jo >> 8, q = jo & 255;
        float s = b_ih0[jo] + b_hh0[jo];
        for (int k = 0; k < E_DIM; k++) s += e[k] * W_ih0[jo * E_DIM + k];
        g_projP[tok * G_DIM + q * 4 + gate] = s;
    }
}

__global__ void init_kernel() {
    int i = blockIdx.x * 256 + threadIdx.x;          // NH threads
    __nv_bfloat16 z = __float2bfloat16(0.0f);
    g_h0hi[NH + i] = z; g_h0lo[NH + i] = z;          // buffer 1 = prev-state at t=0
    g_h1hi[NH + i] = z; g_h1lo[NH + i] = z;
    g_c0[i] = 0.0f; g_c1[i] = 0.0f;
    if (i < N_SEQ) g_acc[i] = 0.0f;
}

__global__ void len_kernel(const int* __restrict__ x) {
    int n = blockIdx.x * 8 + (threadIdx.x >> 5);
    int lane = threadIdx.x & 31;
    int cnt = 0;
    for (int j = lane; j < SEQ_S; j += 32) cnt += (x[n * SEQ_S + j] != 0);
    for (int o = 16; o; o >>= 1) cnt += __shfl_down_sync(0xffffffffu, cnt, o);
    if (lane == 0) g_len[n] = (float)cnt;
}

// ---------------- main: layer1 step tau-1 (bids 0-255, long, scheduled first) +
//                        layer0 step tau   (bids 256-511, short, backfill) ----------------
// CTA tile M=128 x N=128, 8 warps, split-3 bf16 HMMA, k32 chunks, 3-stage pipeline, 2 CTAs/SM.
// Stage recycling via per-stage "consumed" mbarrier (8 warp arrivals) instead of __syncthreads.
__global__ __launch_bounds__(256, 2)
void lstm_mma(const int* __restrict__ x, int tau) {
    extern __shared__ char smraw[];
    const bool isL1 = (blockIdx.x < 256);            // LPT: long CTAs first
    if (!isL1 && tau >= T_STEPS) return;
    if (isL1 && tau == 0) return;
    const int t = isL1 ? tau - 1 : tau;
    const int cta = isL1 ? blockIdx.x : (blockIdx.x - 256);
    const int bM = cta >> 3, bN = cta & 7;
    const int NC = isL1 ? 16 : 8;                    // k=32 per chunk

    unsigned base = smem_u32(smraw);
    unsigned sb = (base + 127u) & ~127u;
    unsigned mbB = sb + NSTAGE * STAGE_BYTES;        // 3 full + 3 consumed mbarriers
    int* tokS = (int*)(smraw + (sb - base) + NSTAGE * STAGE_BYTES + 128);

    const int tid = threadIdx.x;
    if (tid == 0) {
        MBAR_INIT(mbB + 0, 1);  MBAR_INIT(mbB + 8, 1);  MBAR_INIT(mbB + 16, 1);
        MBAR_INIT(mbB + 24, 8); MBAR_INIT(mbB + 32, 8); MBAR_INIT(mbB + 40, 8);
    }
    if (!isL1 && tid < 128) tokS[tid] = x[(bM * 128 + tid) * SEQ_S + t];
    __syncthreads();

    const __nv_bfloat16* Whi = isL1 ? (g_W1hi + bN * 16 * IMG_E) : (g_W0hi + bN * 8 * IMG_E);
    const __nv_bfloat16* Wlo = isL1 ? (g_W1lo + bN * 16 * IMG_E) : (g_W0lo + bN * 8 * IMG_E);

    auto issue = [&](int c, int s) {
        unsigned st = sb + s * STAGE_BYTES;
        const __nv_bfloat16 *ah, *al;
        if (!isL1) {
            size_t o = (size_t)((t + 1) & 1) * NH + (size_t)(c * 32 + bM) * IMG_E;
            ah = g_h0hi + o; al = g_h0lo + o;
        } else if (c < 8) {
            size_t o = (size_t)(t & 1) * NH + (size_t)(c * 32 + bM) * IMG_E;
            ah = g_h0hi + o; al = g_h0lo + o;
        } else {
            size_t o = (size_t)((t + 1) & 1) * NH + (size_t)((c - 8) * 32 + bM) * IMG_E;
            ah = g_h1hi + o; al = g_h1lo + o;
        }
        unsigned mb = mbB + s * 8;
        MBAR_EXPECT(mb, (unsigned)STAGE_BYTES);
        BULK_G2S(st,          ah,                      (unsigned)IMG_B, mb);
        BULK_G2S(st + 8192u,  al,                      (unsigned)IMG_B, mb);
        BULK_G2S(st + 16384u, Whi + (size_t)c * IMG_E, (unsigned)IMG_B, mb);
        BULK_G2S(st + 24576u, Wlo + (size_t)c * IMG_E, (unsigned)IMG_B, mb);
    };

    if (tid == 0) { issue(0, 0); issue(1, 1); issue(2, 2); }

    // per-lane ldmatrix address components (64B-row images)
    const int wid = tid >> 5, lane = tid & 31;
    const int wM = wid & 3, wC = wid >> 2;
    const int rowm = (lane & 7) + ((lane >> 3) & 1) * 8;
    const unsigned khA = (unsigned)(lane >> 4);                    // k-half selector for A
    unsigned offA[2], rxA[2];
#pragma unroll
    for (int mi = 0; mi < 2; mi++) {
        int r = wM * 32 + mi * 16 + rowm;
        offA[mi] = r * 64; rxA[mi] = (r >> 1) & 3;
    }
    const unsigned khB = (unsigned)((lane >> 3) & 1);              // k-half selector for B
    unsigned offB[4], rxB[4];
#pragma unroll
    for (int p = 0; p < 4; p++) {
        int n = wC * 64 + (2 * p + ((lane >> 4) & 1)) * 8 + (lane & 7);
        offB[p] = n * 64; rxB[p] = (n >> 1) & 3;
    }

    float acc[2][8][4];
#pragma unroll
    for (int mi = 0; mi < 2; mi++)
#pragma unroll
        for (int j = 0; j < 8; j++)
#pragma unroll
            for (int r = 0; r < 4; r++) acc[mi][j][r] = 0.0f;

    for (int c = 0; c < NC; c++) {
        const int s = c % NSTAGE;
        mbar_wait(mbB + s * 8, (unsigned)((c / NSTAGE) & 1));
        const unsigned stg = sb + s * STAGE_BYTES;
#pragma unroll
        for (int ks = 0; ks < 2; ks++) {
            uint32_t ahf[2][4], alf[2][4];
#pragma unroll
            for (int mi = 0; mi < 2; mi++) {
                unsigned ad = stg + offA[mi] + ((((unsigned)(ks * 2) + khA) ^ rxA[mi]) << 4);
                LDSM4(ahf[mi][0], ahf[mi][1], ahf[mi][2], ahf[mi][3], ad);
                LDSM4(alf[mi][0], alf[mi][1], alf[mi][2], alf[mi][3], ad + 8192u);
            }
#pragma unroll
            for (int p = 0; p < 4; p++) {
                unsigned bd = stg + 16384u + offB[p] + ((((unsigned)(ks * 2) + khB) ^ rxB[p]) << 4);
                uint32_t b[8];
                LDSM4(b[0], b[1], b[2], b[3], bd);            // Bhi
                LDSM4(b[4], b[5], b[6], b[7], bd + 8192u);    // Blo
                MMA16816(acc[0][2 * p],     ahf[0], b[0], b[1]);
                MMA16816(acc[1][2 * p],     ahf[1], b[0], b[1]);
                MMA16816(acc[0][2 * p + 1], ahf[0], b[2], b[3]);
                MMA16816(acc[1][2 * p + 1], ahf[1], b[2], b[3]);
                MMA16816(acc[0][2 * p],     ahf[0], b[4], b[5]);
                MMA16816(acc[1][2 * p],     ahf[1], b[4], b[5]);
                MMA16816(acc[0][2 * p + 1], ahf[0], b[6], b[7]);
                MMA16816(acc[1][2 * p + 1], ahf[1], b[6], b[7]);
                MMA16816(acc[0][2 * p],     alf[0], b[0], b[1]);
                MMA16816(acc[1][2 * p],     alf[1], b[0], b[1]);
                MMA16816(acc[0][2 * p + 1], alf[0], b[2], b[3]);
                MMA16816(acc[1][2 * p + 1], alf[1], b[2], b[3]);
            }
        }
        // stage consumed: one arrival per warp; compute warps proceed immediately
        if (lane == 0) MBAR_ARRIVE(mbB + 24 + s * 8);
        // producer: wait all 8 consumers of this stage epoch, then recycle it
        if (tid == 0 && c + NSTAGE < NC) {
            mbar_wait(mbB + 24 + s * 8, (unsigned)((c / NSTAGE) & 1));
            asm volatile("fence.proxy.async;" ::: "memory");
            issue(c + NSTAGE, s);
        }
    }

    // ---- epilogue: gates (register-local quadruples) -> LSTM pointwise -> swizzled h images ----
    float* cst = isL1 ? g_c1 : g_c0;
    __nv_bfloat16* ohi = (isL1 ? g_h1hi : g_h0hi) + (size_t)(t & 1) * NH;
    __nv_bfloat16* olo = (isL1 ? g_h1lo : g_h0lo) + (size_t)(t & 1) * NH;
    const int gID = lane >> 2, a4 = lane & 3;
#pragma unroll
    for (int mi = 0; mi < 2; mi++) {
#pragma unroll
        for (int rs = 0; rs < 2; rs++) {
            const int rloc = wM * 32 + mi * 16 + gID + rs * 8;
            const int n = bM * 128 + rloc;
            const float* bias4 = isL1 ? g_b1U : (g_projP + (size_t)tokS[rloc] * G_DIM);
#pragma unroll
            for (int jp = 0; jp < 4; jp++) {
                const int un = bN * 32 + wC * 16 + a4 * 4 + jp;
                float4 bb = *(const float4*)&bias4[un * 4];
                float gi = acc[mi][2 * jp][rs * 2 + 0] + bb.x;
                float gf = acc[mi][2 * jp][rs * 2 + 1] + bb.y;
                float gg = acc[mi][2 * jp + 1][rs * 2 + 0] + bb.z;
                float go = acc[mi][2 * jp + 1][rs * 2 + 1] + bb.w;
                size_t ci = (size_t)n * H_DIM + un;
                float ii = fsig(gi), ff = fsig(gf), gv = ftanh(gg), oo = fsig(go);
                float cn = ff * cst[ci] + ii * gv;
                cst[ci] = cn;
                float h = oo * ftanh(cn);
                __nv_bfloat16 hh = __float2bfloat16(h);
                __nv_bfloat16 hl = __float2bfloat16(h - __bfloat162float(hh));
                int off = ((un >> 5) * 32 + bM) * IMG_E + eoff32(rloc, un & 31);
                ohi[off] = hh; olo[off] = hl;
                if (isL1) g_h1f[(size_t)t * NH + ci] = h;
            }
        }
    }
}

// ---------------- fc + relu + log_softmax + probs + masked NLL ----------------
__global__ __launch_bounds__(288)
void fc_kernel(const float* __restrict__ fc_W, const float* __restrict__ fc_b,
               const int* __restrict__ x, float* __restrict__ out) {
    __shared__ float Ws[VOCAB][H_DIM + 1];
    __shared__ float hs[8][H_DIM];
    __shared__ float lg[8][VOCAB + 2];
    __shared__ float lse_s[8];

    const int t = blockIdx.y;
    const int n0 = blockIdx.x * 8;
    const int tid = threadIdx.x;

    for (int i = tid; i < VOCAB * H_DIM; i += 288) Ws[i / H_DIM][i % H_DIM] = fc_W[i];
    const float* hsrc = g_h1f + (size_t)t * NH + (size_t)n0 * H_DIM;
    for (int i = tid; i < 8 * H_DIM; i += 288) hs[i / H_DIM][i % H_DIM] = hsrc[i];
    __syncthreads();

    int s = tid / VOCAB;
    int v = tid - s * VOCAB;
    float a = fc_b[v];
#pragma unroll 8
    for (int k = 0; k < H_DIM; k++) a += hs[s][k] * Ws[v][k];
    float l = fmaxf(a, 0.0f);
    lg[s][v] = l;
    __syncthreads();

    if (v == 0) {
        float m = -1e30f;
        for (int j = 0; j < VOCAB; j++) m = fmaxf(m, lg[s][j]);
        float sum = 0.0f;
        for (int j = 0; j < VOCAB; j++) sum += expf(lg[s][j] - m);
        lse_s[s] = m + logf(sum);
    }
    __syncthreads();

    float lse = lse_s[s];
    int n = n0 + s;
    out[((size_t)n * T_STEPS + t) * VOCAB + v] = expf(l - lse);
    int tgt = x[n * SEQ_S + t + 1];
    if (v == tgt && tgt != 0) atomicAdd(&g_acc[n], lse - l);
}

__global__ void finalize_kernel(float* __restrict__ out) {
    __shared__ float red[1024];
    int tid = threadIdx.x;
    float sum = 0.0f;
    for (int n = tid; n < N_SEQ; n += 1024) {
        float ml = g_acc[n] / g_len[n];
        out[PROBS_OFF + n] = ml;
        sum += ml;
    }
    red[tid] = sum;
    __syncthreads();
    for (int sft = 512; sft > 0; sft >>= 1) {
        if (tid < sft) red[tid] += red[tid + sft];
        __syncthreads();
    }
    if (tid == 0) out[PROBS_OFF + N_SEQ] = red[0] / (float)N_SEQ;
}

// ---------------- launch (ordered so ncu -s 5 captures lstm_mma) ----------------
extern "C" void kernel_launch(void* const* d_in, const int* in_sizes, int n_in,
                              void* d_out, int out_size) {
    const int*   x     = (const int*)  d_in[0];
    const float* emb   = (const float*)d_in[1];
    const float* W_ih0 = (const float*)d_in[2];
    const float* W_hh0 = (const float*)d_in[3];
    const float* b_ih0 = (const float*)d_in[4];
    const float* b_hh0 = (const float*)d_in[5];
    const float* W_ih1 = (const float*)d_in[6];
    const float* W_hh1 = (const float*)d_in[7];
    const float* b_ih1 = (const float*)d_in[8];
    const float* b_hh1 = (const float*)d_in[9];
    const float* fc_W  = (const float*)d_in[10];
    const float* fc_b  = (const float*)d_in[11];
    float* out = (float*)d_out;

    cudaFuncSetAttribute(lstm_mma, cudaFuncAttributeMaxDynamicSharedMemorySize, SMEM_SZ);

    len_kernel<<<N_SEQ / 8, 256>>>(x);                                   // launch 0
    init_kernel<<<NH / 256, 256>>>();                                    // launch 1
    prep_proj<<<VOCAB, 256>>>(emb, W_ih0, b_ih0, b_hh0);                 // launch 2
    prep_w<<<G_DIM, 128>>>(W_hh0, W_ih1, W_hh1, b_ih1, b_hh1);           // launch 3

    for (int tau = 0; tau <= T_STEPS; tau++)                             // launches 4..131
        lstm_mma<<<512, 256, SMEM_SZ>>>(x, tau);

    fc_kernel<<<dim3(N_SEQ / 8, T_STEPS), 288>>>(fc_W, fc_b, x, out);
    finalize_kernel<<<1, 1024>>>(out);
}

// round 15
// speedup vs baseline: 1.0501x; 1.0501x over previous
#include <cuda_runtime.h>
#include <cuda_bf16.h>
#include <math.h>
#include <stdint.h>

#define N_SEQ 4096
#define SEQ_S 128
#define T_STEPS 127
#define VOCAB 36
#define E_DIM 128
#define H_DIM 256
#define G_DIM 1024
#define NH (N_SEQ * H_DIM)             // 1048576 elems per h plane
#define IMG_E 4096                      // elems per 128x32 bf16 image (8KB)
#define IMG_B 8192                      // bytes per image
#define STAGE_BYTES 32768               // Ahi/Alo/Bhi/Blo 8KB each
#define NSTAGE 3
#define SMEM_SZ 99456

static const size_t PROBS_OFF = (size_t)N_SEQ * T_STEPS * VOCAB;  // 18726912

// ---------------- device scratch (no allocations allowed) ----------------
__device__ __align__(128) __nv_bfloat16 g_W0hi[8 * 8 * IMG_E],  g_W0lo[8 * 8 * IMG_E];
__device__ __align__(128) __nv_bfloat16 g_W1hi[8 * 16 * IMG_E], g_W1lo[8 * 16 * IMG_E];
__device__ __align__(128) __nv_bfloat16 g_h0hi[2 * NH], g_h0lo[2 * NH];   // swizzled k32 images
__device__ __align__(128) __nv_bfloat16 g_h1hi[2 * NH], g_h1lo[2 * NH];
__device__ __align__(128) float g_h1f[(size_t)T_STEPS * NH];              // fp32 h1 history for fc
__device__ __align__(128) float g_projP[VOCAB * G_DIM];                   // emb@W_ih0^T + b, unit-major
__device__ __align__(128) float g_b1U[G_DIM];
__device__ __align__(128) float g_c0[NH], g_c1[NH];
__device__ float g_acc[N_SEQ], g_len[N_SEQ];
__device__ unsigned g_bar;                                                // grid barrier counter

// ---------------- helpers ----------------
__device__ __forceinline__ unsigned smem_u32(const void* p) {
    unsigned a;
    asm("{ .reg .u64 t; cvta.to.shared.u64 t, %1; cvt.u32.u64 %0, t; }" : "=r"(a) : "l"(p));
    return a;
}
// elem offset inside a 128x32 bf16 image, 64B rows, conflict-free ldmatrix swizzle
__device__ __forceinline__ int eoff32(int r, int kk) {
    return r * 32 + ((((kk >> 3) ^ ((r >> 1) & 3)) & 3) << 3) + (kk & 7);
}
__device__ __forceinline__ float fsig(float x) { return __fdividef(1.0f, 1.0f + __expf(-x)); }
__device__ __forceinline__ float ftanh(float x) { return __fdividef(2.0f, 1.0f + __expf(-2.0f * x)) - 1.0f; }

#define MBAR_INIT(addr, cnt) \
    asm volatile("mbarrier.init.shared.b64 [%0], %1;" :: "r"(addr), "r"(cnt) : "memory")
#define MBAR_EXPECT(addr, tx) \
    asm volatile("mbarrier.arrive.expect_tx.shared.b64 _, [%0], %1;" :: "r"(addr), "r"(tx) : "memory")
#define BULK_G2S(dst, src, bytes, mb) \
    asm volatile("cp.async.bulk.shared::cta.global.mbarrier::complete_tx::bytes [%0], [%1], %2, [%3];" \
                 :: "r"(dst), "l"(src), "r"(bytes), "r"(mb) : "memory")

__device__ __forceinline__ void mbar_wait(unsigned addr, unsigned parity) {
    unsigned done;
    asm volatile("{\n\t.reg .pred p;\n\t"
                 "mbarrier.try_wait.parity.acquire.cta.shared::cta.b64 p, [%1], %2;\n\t"
                 "selp.b32 %0, 1, 0, p;\n\t}" : "=r"(done) : "r"(addr), "r"(parity) : "memory");
    if (!done) {
        asm volatile("{\n\t.reg .pred P1;\n\t"
                     "WL_%=:\n\t"
                     "mbarrier.try_wait.parity.acquire.cta.shared::cta.b64 P1, [%0], %1, 0x989680;\n\t"
                     "@P1 bra.uni WD_%=;\n\t"
                     "bra.uni WL_%=;\n\t"
                     "WD_%=:\n\t}" :: "r"(addr), "r"(parity) : "memory");
    }
}

#define LDSM4(r0, r1, r2, r3, addr) \
    asm volatile("ldmatrix.sync.aligned.m8n8.x4.shared.b16 {%0,%1,%2,%3}, [%4];" \
                 : "=r"(r0), "=r"(r1), "=r"(r2), "=r"(r3) : "r"(addr))

#define MMA16816(d, a, b0, b1) \
    asm volatile("mma.sync.aligned.m16n8k16.row.col.f32.bf16.bf16.f32 " \
                 "{%0,%1,%2,%3}, {%4,%5,%6,%7}, {%8,%9}, {%0,%1,%2,%3};" \
                 : "+f"((d)[0]), "+f"((d)[1]), "+f"((d)[2]), "+f"((d)[3]) \
                 : "r"((a)[0]), "r"((a)[1]), "r"((a)[2]), "r"((a)[3]), "r"(b0), "r"(b1))

// ---------------- shared GEMM building blocks ----------------
// issue one k32 chunk's 4 bulk copies into stage at smem 'st', barrier 'mb'
__device__ __forceinline__ void issue_chunk(bool isL1, int t, int bM, int bN, int c,
                                            unsigned st, unsigned mb) {
    const __nv_bfloat16 *ah, *al, *wh, *wl;
    if (!isL1) {
        size_t o = (size_t)((t + 1) & 1) * NH + (size_t)(c * 32 + bM) * IMG_E;
        ah = g_h0hi + o; al = g_h0lo + o;
        wh = g_W0hi + (size_t)(bN * 8 + c) * IMG_E;
        wl = g_W0lo + (size_t)(bN * 8 + c) * IMG_E;
    } else if (c < 8) {
        size_t o = (size_t)(t & 1) * NH + (size_t)(c * 32 + bM) * IMG_E;
        ah = g_h0hi + o; al = g_h0lo + o;
        wh = g_W1hi + (size_t)(bN * 16 + c) * IMG_E;
        wl = g_W1lo + (size_t)(bN * 16 + c) * IMG_E;
    } else {
        size_t o = (size_t)((t + 1) & 1) * NH + (size_t)((c - 8) * 32 + bM) * IMG_E;
        ah = g_h1hi + o; al = g_h1lo + o;
        wh = g_W1hi + (size_t)(bN * 16 + c) * IMG_E;
        wl = g_W1lo + (size_t)(bN * 16 + c) * IMG_E;
    }
    MBAR_EXPECT(mb, (unsigned)STAGE_BYTES);
    BULK_G2S(st,          ah, (unsigned)IMG_B, mb);
    BULK_G2S(st + 8192u,  al, (unsigned)IMG_B, mb);
    BULK_G2S(st + 16384u, wh, (unsigned)IMG_B, mb);
    BULK_G2S(st + 24576u, wl, (unsigned)IMG_B, mb);
}

// one k32 chunk of split-3 bf16 HMMA into acc
__device__ __forceinline__ void compute_chunk(unsigned stg, float acc[2][8][4],
                                              const unsigned offA[2], const unsigned rxA[2], unsigned khA,
                                              const unsigned offB[4], const unsigned rxB[4], unsigned khB) {
#pragma unroll
    for (int ks = 0; ks < 2; ks++) {
        uint32_t ahf[2][4], alf[2][4];
#pragma unroll
        for (int mi = 0; mi < 2; mi++) {
            unsigned ad = stg + offA[mi] + ((((unsigned)(ks * 2) + khA) ^ rxA[mi]) << 4);
            LDSM4(ahf[mi][0], ahf[mi][1], ahf[mi][2], ahf[mi][3], ad);
            LDSM4(alf[mi][0], alf[mi][1], alf[mi][2], alf[mi][3], ad + 8192u);
        }
#pragma unroll
        for (int p = 0; p < 4; p++) {
            unsigned bd = stg + 16384u + offB[p] + ((((unsigned)(ks * 2) + khB) ^ rxB[p]) << 4);
            uint32_t b[8];
            LDSM4(b[0], b[1], b[2], b[3], bd);            // Bhi
            LDSM4(b[4], b[5], b[6], b[7], bd + 8192u);    // Blo
            MMA16816(acc[0][2 * p],     ahf[0], b[0], b[1]);
            MMA16816(acc[1][2 * p],     ahf[1], b[0], b[1]);
            MMA16816(acc[0][2 * p + 1], ahf[0], b[2], b[3]);
            MMA16816(acc[1][2 * p + 1], ahf[1], b[2], b[3]);
            MMA16816(acc[0][2 * p],     ahf[0], b[4], b[5]);
            MMA16816(acc[1][2 * p],     ahf[1], b[4], b[5]);
            MMA16816(acc[0][2 * p + 1], ahf[0], b[6], b[7]);
            MMA16816(acc[1][2 * p + 1], ahf[1], b[6], b[7]);
            MMA16816(acc[0][2 * p],     alf[0], b[0], b[1]);
            MMA16816(acc[1][2 * p],     alf[1], b[0], b[1]);
            MMA16816(acc[0][2 * p + 1], alf[0], b[2], b[3]);
            MMA16816(acc[1][2 * p + 1], alf[1], b[2], b[3]);
        }
    }
}

// gates -> LSTM pointwise -> swizzled hi/lo h images (+ fp32 h1 history)
__device__ __forceinline__ void epilogue_job(bool isL1, int t, int bM, int bN,
                                             float acc[2][8][4], int wM, int wC, int lane,
                                             const int* tokS) {
    float* cst = isL1 ? g_c1 : g_c0;
    __nv_bfloat16* ohi = (isL1 ? g_h1hi : g_h0hi) + (size_t)(t & 1) * NH;
    __nv_bfloat16* olo = (isL1 ? g_h1lo : g_h0lo) + (size_t)(t & 1) * NH;
    const int gID = lane >> 2, a4 = lane & 3;
#pragma unroll
    for (int mi = 0; mi < 2; mi++) {
#pragma unroll
        for (int rs = 0; rs < 2; rs++) {
            const int rloc = wM * 32 + mi * 16 + gID + rs * 8;
            const int n = bM * 128 + rloc;
            const float* bias4 = isL1 ? g_b1U : (g_projP + (size_t)tokS[rloc] * G_DIM);
#pragma unroll
            for (int jp = 0; jp < 4; jp++) {
                const int un = bN * 32 + wC * 16 + a4 * 4 + jp;
                float4 bb = *(const float4*)&bias4[un * 4];
                float gi = acc[mi][2 * jp][rs * 2 + 0] + bb.x;
                float gf = acc[mi][2 * jp][rs * 2 + 1] + bb.y;
                float gg = acc[mi][2 * jp + 1][rs * 2 + 0] + bb.z;
                float go = acc[mi][2 * jp + 1][rs * 2 + 1] + bb.w;
                size_t ci = (size_t)n * H_DIM + un;
                float ii = fsig(gi), ff = fsig(gf), gv = ftanh(gg), oo = fsig(go);
                float cn = ff * cst[ci] + ii * gv;
                cst[ci] = cn;
                float h = oo * ftanh(cn);
                __nv_bfloat16 hh = __float2bfloat16(h);
                __nv_bfloat16 hl = __float2bfloat16(h - __bfloat162float(hh));
                int off = ((un >> 5) * 32 + bM) * IMG_E + eoff32(rloc, un & 31);
                ohi[off] = hh; olo[off] = hl;
                if (isL1) g_h1f[(size_t)t * NH + ci] = h;
            }
        }
    }
}

// ---------------- prep kernels ----------------
__device__ __forceinline__ int perm_nloc(int gate, int q, int& blockN) {
    blockN = q >> 5;
    int rem = q & 31, wcol = rem >> 4, rem2 = rem & 15, a = rem2 >> 2, jp = rem2 & 3;
    return wcol * 64 + 2 * a + 16 * jp + 8 * (gate >> 1) + (gate & 1);
}

__global__ void prep_w(const float* __restrict__ W_hh0,
                       const float* __restrict__ W_ih1, const float* __restrict__ W_hh1,
                       const float* __restrict__ b_ih1, const float* __restrict__ b_hh1) {
    int jo = blockIdx.x, tid = threadIdx.x;          // original gate row 0..1023
    int gate = jo >> 8, q = jo & 255;
    int bN;
    int nloc = perm_nloc(gate, q, bN);
    for (int k = tid; k < H_DIM; k += 128) {         // W0 = W_hh0 only (ih0 folded into proj)
        float v = W_hh0[jo * H_DIM + k];
        __nv_bfloat16 hi = __float2bfloat16(v);
        __nv_bfloat16 lo = __float2bfloat16(v - __bfloat162float(hi));
        int idx = (bN * 8 + (k >> 5)) * IMG_E + eoff32(nloc, k & 31);
        g_W0hi[idx] = hi; g_W0lo[idx] = lo;
    }
    for (int k = tid; k < 512; k += 128) {           // W1 = [W_ih1 | W_hh1]
        float v = (k < H_DIM) ? W_ih1[jo * H_DIM + k] : W_hh1[jo * H_DIM + k - H_DIM];
        __nv_bfloat16 hi = __float2bfloat16(v);
        __nv_bfloat16 lo = __float2bfloat16(v - __bfloat162float(hi));
        int idx = (bN * 16 + (k >> 5)) * IMG_E + eoff32(nloc, k & 31);
        g_W1hi[idx] = hi; g_W1lo[idx] = lo;
    }
    if (tid == 0) g_b1U[q * 4 + gate] = b_ih1[jo] + b_hh1[jo];
}

__global__ void prep_proj(const float* __restrict__ emb, const float* __restrict__ W_ih0,
                          const float* __restrict__ b_ih0, const float* __restrict__ b_hh0) {
    __shared__ float e[E_DIM];
    int tok = blockIdx.x, tid = threadIdx.x;
    if (tid < E_DIM) e[tid] = emb[tok * E_DIM + tid];
    __syncthreads();
    for (int jo = tid; jo < G_DIM; jo += 256) {
        int gate = jo >> 8, q = jo & 255;
        float s = b_ih0[jo] + b_hh0[jo];
        for (int k = 0; k < E_DIM; k++) s += e[k] * W_ih0[jo * E_DIM + k];
        g_projP[tok * G_DIM + q * 4 + gate] = s;
    }
}

__global__ void init_kernel() {
    int i = blockIdx.x * 256 + threadIdx.x;          // NH threads
    __nv_bfloat16 z = __float2bfloat16(0.0f);
    g_h0hi[NH + i] = z; g_h0lo[NH + i] = z;          // buffer 1 = prev-state at t=0
    g_h1hi[NH + i] = z; g_h1lo[NH + i] = z;
    g_c0[i] = 0.0f; g_c1[i] = 0.0f;
    if (i < N_SEQ) g_acc[i] = 0.0f;
    if (i == 0) g_bar = 0u;
}

__global__ void len_kernel(const int* __restrict__ x) {
    int n = blockIdx.x * 8 + (threadIdx.x >> 5);
    int lane = threadIdx.x & 31;
    int cnt = 0;
    for (int j = lane; j < SEQ_S; j += 32) cnt += (x[n * SEQ_S + j] != 0);
    for (int o = 16; o; o >>= 1) cnt += __shfl_down_sync(0xffffffffu, cnt, o);
    if (lane == 0) g_len[n] = (float)cnt;
}

// ================= persistent fused LSTM: all 128 tau-phases in one launch =================
// Tile list: ids 0..255 = L1 tiles, 256..511 = L0 tiles. CTA b owns tiles b and b+gridDim.x.
// gridDim.x >= 256 guarantees the second tile (if any) is L0. Grid barrier between phases.
__global__ __launch_bounds__(256, 2)
void lstm_persist(const int* __restrict__ x) {
    extern __shared__ char smraw[];
    unsigned base = smem_u32(smraw);
    unsigned sb = (base + 127u) & ~127u;
    unsigned mbB = sb + NSTAGE * STAGE_BYTES;
    int* tokS = (int*)(smraw + (sb - base) + NSTAGE * STAGE_BYTES + 128);

    const int tid = threadIdx.x;
    const int bid = blockIdx.x;
    const int NCTA = gridDim.x;

    if (tid == 0) { MBAR_INIT(mbB + 0, 1); MBAR_INIT(mbB + 8, 1); MBAR_INIT(mbB + 16, 1); }
    __syncthreads();

    // static jobs
    const bool j0L1 = (bid < 256);
    const int cta0 = j0L1 ? bid : (bid - 256);
    const int id1 = bid + NCTA;
    const bool j1v = (id1 < 512);                    // job1, when valid, is always L0
    const int cta1 = j1v ? (id1 - 256) : 0;
    const int bM0 = cta0 >> 3, bN0 = cta0 & 7;
    const int bM1 = cta1 >> 3, bN1 = cta1 & 7;
    const int ctaL0 = j0L1 ? (j1v ? cta1 : -1) : cta0;
    const int bML0 = (ctaL0 >= 0) ? (ctaL0 >> 3) : 0;

    // per-lane ldmatrix addressing
    const int wid = tid >> 5, lane = tid & 31;
    const int wM = wid & 3, wC = wid >> 2;
    const int rowm = (lane & 7) + ((lane >> 3) & 1) * 8;
    const unsigned khA = (unsigned)(lane >> 4);
    unsigned offA[2], rxA[2];
#pragma unroll
    for (int mi = 0; mi < 2; mi++) {
        int r = wM * 32 + mi * 16 + rowm;
        offA[mi] = r * 64; rxA[mi] = (r >> 1) & 3;
    }
    const unsigned khB = (unsigned)((lane >> 3) & 1);
    unsigned offB[4], rxB[4];
#pragma unroll
    for (int p = 0; p < 4; p++) {
        int n = wC * 64 + (2 * p + ((lane >> 4) & 1)) * 8 + (lane & 7);
        offB[p] = n * 64; rxB[p] = (n >> 1) & 3;
    }

    unsigned ph0 = 0, ph1 = 0, ph2 = 0;              // per-stage mbarrier parities
    float acc[2][8][4];
#pragma unroll
    for (int mi = 0; mi < 2; mi++)
#pragma unroll
        for (int j = 0; j < 8; j++)
#pragma unroll
            for (int r = 0; r < 4; r++) acc[mi][j][r] = 0.0f;

    for (int tau = 0; tau <= T_STEPS; tau++) {
        const int nA = j0L1 ? (tau >= 1 ? 16 : 0) : (tau < T_STEPS ? 8 : 0);
        const int nB = (j1v && tau < T_STEPS) ? 8 : 0;
        const int total = nA + nB;

        if (total > 0) {
            if (ctaL0 >= 0 && tau < T_STEPS && tid < 128)
                tokS[tid] = x[(bML0 * 128 + tid) * SEQ_S + tau];
            __syncthreads();

            if (tid == 0) {
                asm volatile("fence.proxy.async;" ::: "memory");
                const int pre = total < NSTAGE ? total : NSTAGE;
                for (int p = 0; p < pre; p++) {
                    unsigned st = sb + p * STAGE_BYTES, mb = mbB + p * 8;
                    if (p < nA) issue_chunk(j0L1, j0L1 ? tau - 1 : tau, bM0, bN0, p, st, mb);
                    else        issue_chunk(false, tau, bM1, bN1, p - nA, st, mb);
                }
            }

            for (int i = 0; i < total; i++) {
                const int s = i % NSTAGE;
                unsigned par = (s == 0) ? ph0 : ((s == 1) ? ph1 : ph2);
                mbar_wait(mbB + s * 8, par);
                if (s == 0) ph0 ^= 1; else if (s == 1) ph1 ^= 1; else ph2 ^= 1;

                compute_chunk(sb + s * STAGE_BYTES, acc, offA, rxA, khA, offB, rxB, khB);
                __syncthreads();

                if (tid == 0 && i + NSTAGE < total) {
                    asm volatile("fence.proxy.async;" ::: "memory");
                    const int nx = i + NSTAGE;
                    unsigned st = sb + s * STAGE_BYTES, mb = mbB + s * 8;
                    if (nx < nA) issue_chunk(j0L1, j0L1 ? tau - 1 : tau, bM0, bN0, nx, st, mb);
                    else         issue_chunk(false, tau, bM1, bN1, nx - nA, st, mb);
                }

                if (nA > 0 && i == nA - 1) {
                    epilogue_job(j0L1, j0L1 ? tau - 1 : tau, bM0, bN0, acc, wM, wC, lane, tokS);
#pragma unroll
                    for (int mi = 0; mi < 2; mi++)
#pragma unroll
                        for (int j = 0; j < 8; j++)
#pragma unroll
                            for (int r = 0; r < 4; r++) acc[mi][j][r] = 0.0f;
                }
                if (nB > 0 && i == total - 1) {
                    epilogue_job(false, tau, bM1, bN1, acc, wM, wC, lane, tokS);
#pragma unroll
                    for (int mi = 0; mi < 2; mi++)
#pragma unroll
                        for (int j = 0; j < 8; j++)
#pragma unroll
                            for (int r = 0; r < 4; r++) acc[mi][j][r] = 0.0f;
                }
            }
        }

        // -------- grid barrier between phases --------
        __threadfence();
        __syncthreads();
        if (tid == 0) {
            atomicAdd(&g_bar, 1u);
            const unsigned tgt = (unsigned)NCTA * (unsigned)(tau + 1);
            while (*((volatile unsigned*)&g_bar) < tgt) __nanosleep(64);
        }
        __syncthreads();
    }
}

// ================= fallback: per-tau launches (R13 structure, proven 10.79ms) =================
__global__ __launch_bounds__(256, 2)
void lstm_mma(const int* __restrict__ x, int tau) {
    extern __shared__ char smraw[];
    const bool isL1 = (blockIdx.x & 1);
    if (!isL1 && tau >= T_STEPS) return;
    if (isL1 && tau == 0) return;
    const int t = isL1 ? tau - 1 : tau;
    const int cta = blockIdx.x >> 1;
    const int bM = cta >> 3, bN = cta & 7;
    const int NC = isL1 ? 16 : 8;

    unsigned base = smem_u32(smraw);
    unsigned sb = (base + 127u) & ~127u;
    unsigned mbB = sb + NSTAGE * STAGE_BYTES;
    int* tokS = (int*)(smraw + (sb - base) + NSTAGE * STAGE_BYTES + 128);

    const int tid = threadIdx.x;
    if (tid == 0) { MBAR_INIT(mbB + 0, 1); MBAR_INIT(mbB + 8, 1); MBAR_INIT(mbB + 16, 1); }
    if (!isL1 && tid < 128) tokS[tid] = x[(bM * 128 + tid) * SEQ_S + t];
    __syncthreads();

    if (tid == 0)
        for (int p = 0; p < NSTAGE && p < NC; p++)
            issue_chunk(isL1, t, bM, bN, p, sb + p * STAGE_BYTES, mbB + p * 8);

    const int wid = tid >> 5, lane = tid & 31;
    const int wM = wid & 3, wC = wid >> 2;
    const int rowm = (lane & 7) + ((lane >> 3) & 1) * 8;
    const unsigned khA = (unsigned)(lane >> 4);
    unsigned offA[2], rxA[2];
#pragma unroll
    for (int mi = 0; mi < 2; mi++) {
        int r = wM * 32 + mi * 16 + rowm;
        offA[mi] = r * 64; rxA[mi] = (r >> 1) & 3;
    }
    const unsigned khB = (unsigned)((lane >> 3) & 1);
    unsigned offB[4], rxB[4];
#pragma unroll
    for (int p = 0; p < 4; p++) {
        int n = wC * 64 + (2 * p + ((lane >> 4) & 1)) * 8 + (lane & 7);
        offB[p] = n * 64; rxB[p] = (n >> 1) & 3;
    }

    float acc[2][8][4];
#pragma unroll
    for (int mi = 0; mi < 2; mi++)
#pragma unroll
        for (int j = 0; j < 8; j++)
#pragma unroll
            for (int r = 0; r < 4; r++) acc[mi][j][r] = 0.0f;

    for (int c = 0; c < NC; c++) {
        const int s = c % NSTAGE;
        mbar_wait(mbB + s * 8, (unsigned)((c / NSTAGE) & 1));
        compute_chunk(sb + s * STAGE_BYTES, acc, offA, rxA, khA, offB, rxB, khB);
        __syncthreads();
        if (tid == 0 && c + NSTAGE < NC)
            issue_chunk(isL1, t, bM, bN, c + NSTAGE, sb + s * STAGE_BYTES, mbB + s * 8);
    }
    epilogue_job(isL1, t, bM, bN, acc, wM, wC, lane, tokS);
}

// ---------------- fc + relu + log_softmax + probs + masked NLL ----------------
__global__ __launch_bounds__(288)
void fc_kernel(const float* __restrict__ fc_W, const float* __restrict__ fc_b,
               const int* __restrict__ x, float* __restrict__ out) {
    __shared__ float Ws[VOCAB][H_DIM + 1];
    __shared__ float hs[8][H_DIM];
    __shared__ float lg[8][VOCAB + 2];
    __shared__ float lse_s[8];

    const int t = blockIdx.y;
    const int n0 = blockIdx.x * 8;
    const int tid = threadIdx.x;

    for (int i = tid; i < VOCAB * H_DIM; i += 288) Ws[i / H_DIM][i % H_DIM] = fc_W[i];
    const float* hsrc = g_h1f + (size_t)t * NH + (size_t)n0 * H_DIM;
    for (int i = tid; i < 8 * H_DIM; i += 288) hs[i / H_DIM][i % H_DIM] = hsrc[i];
    __syncthreads();

    int s = tid / VOCAB;
    int v = tid - s * VOCAB;
    float a = fc_b[v];
#pragma unroll 8
    for (int k = 0; k < H_DIM; k++) a += hs[s][k] * Ws[v][k];
    float l = fmaxf(a, 0.0f);
    lg[s][v] = l;
    __syncthreads();

    if (v == 0) {
        float m = -1e30f;
        for (int j = 0; j < VOCAB; j++) m = fmaxf(m, lg[s][j]);
        float sum = 0.0f;
        for (int j = 0; j < VOCAB; j++) sum += expf(lg[s][j] - m);
        lse_s[s] = m + logf(sum);
    }
    __syncthreads();

    float lse = lse_s[s];
    int n = n0 + s;
    out[((size_t)n * T_STEPS + t) * VOCAB + v] = expf(l - lse);
    int tgt = x[n * SEQ_S + t + 1];
    if (v == tgt && tgt != 0) atomicAdd(&g_acc[n], lse - l);
}

__global__ void finalize_kernel(float* __restrict__ out) {
    __shared__ float red[1024];
    int tid = threadIdx.x;
    float sum = 0.0f;
    for (int n = tid; n < N_SEQ; n += 1024) {
        float ml = g_acc[n] / g_len[n];
        out[PROBS_OFF + n] = ml;
        sum += ml;
    }
    red[tid] = sum;
    __syncthreads();
    for (int sft = 512; sft > 0; sft >>= 1) {
        if (tid < sft) red[tid] += red[tid + sft];
        __syncthreads();
    }
    if (tid == 0) out[PROBS_OFF + N_SEQ] = red[0] / (float)N_SEQ;
}

// ---------------- launch (persistent kernel is launch index 3 for ncu) ----------------
extern "C" void kernel_launch(void* const* d_in, const int* in_sizes, int n_in,
                              void* d_out, int out_size) {
    const int*   x     = (const int*)  d_in[0];
    const float* emb   = (const float*)d_in[1];
    const float* W_ih0 = (const float*)d_in[2];
    const float* W_hh0 = (const float*)d_in[3];
    const float* b_ih0 = (const float*)d_in[4];
    const float* b_hh0 = (const float*)d_in[5];
    const float* W_ih1 = (const float*)d_in[6];
    const float* W_hh1 = (const float*)d_in[7];
    const float* b_ih1 = (const float*)d_in[8];
    const float* b_hh1 = (const float*)d_in[9];
    const float* fc_W  = (const float*)d_in[10];
    const float* fc_b  = (const float*)d_in[11];
    float* out = (float*)d_out;

    cudaFuncSetAttribute(lstm_persist, cudaFuncAttributeMaxDynamicSharedMemorySize, SMEM_SZ);
    cudaFuncSetAttribute(lstm_mma, cudaFuncAttributeMaxDynamicSharedMemorySize, SMEM_SZ);

    init_kernel<<<NH / 256, 256>>>();                                    // launch 0
    prep_proj<<<VOCAB, 256>>>(emb, W_ih0, b_ih0, b_hh0);                 // launch 1
    prep_w<<<G_DIM, 128>>>(W_hh0, W_ih1, W_hh1, b_ih1, b_hh1);           // launch 2

    // choose persistent vs per-tau path (deterministic host-side query; no device work)
    int occ = 0, sms = 0, dev = 0;
    cudaGetDevice(&dev);
    cudaOccupancyMaxActiveBlocksPerMultiprocessor(&occ, lstm_persist, 256, SMEM_SZ);
    cudaDeviceGetAttribute(&sms, cudaDevAttrMultiProcessorCount, dev);
    long resident = (long)occ * (long)sms;
    int ncta = (int)(resident < 512 ? resident : 512);

    if (occ >= 2 && ncta >= 256) {
        lstm_persist<<<ncta, 256, SMEM_SZ>>>(x);                         // launch 3 (profiled)
    } else {
        for (int tau = 0; tau <= T_STEPS; tau++)
            lstm_mma<<<512, 256, SMEM_SZ>>>(x, tau);
    }

    len_kernel<<<N_SEQ / 8, 256>>>(x);
    fc_kernel<<<dim3(N_SEQ / 8, T_STEPS), 288>>>(fc_W, fc_b, x, out);
    finalize_kernel<<<1, 1024>>>(out);
}

// round 16
// speedup vs baseline: 1.1195x; 1.0661x over previous
#include <cuda_runtime.h>
#include <cuda_bf16.h>
#include <math.h>
#include <stdint.h>

#define N_SEQ 4096
#define SEQ_S 128
#define T_STEPS 127
#define VOCAB 36
#define E_DIM 128
#define H_DIM 256
#define G_DIM 1024
#define NH (N_SEQ * H_DIM)             // 1048576 elems per h plane
#define IMG_E 4096                      // elems per 128x32 bf16 image (8KB)
#define IMG_B 8192                      // bytes per image
#define STAGE_BYTES 32768               // Ahi/Alo/Bhi/Blo 8KB each
#define NSTAGE 3
#define SMEM_SZ 99456
#define NTHR 512                        // 16 warps per CTA

static const size_t PROBS_OFF = (size_t)N_SEQ * T_STEPS * VOCAB;  // 18726912

// ---------------- device scratch (no allocations allowed) ----------------
__device__ __align__(128) __nv_bfloat16 g_W0hi[8 * 8 * IMG_E],  g_W0lo[8 * 8 * IMG_E];
__device__ __align__(128) __nv_bfloat16 g_W1hi[8 * 16 * IMG_E], g_W1lo[8 * 16 * IMG_E];
__device__ __align__(128) __nv_bfloat16 g_h0hi[2 * NH], g_h0lo[2 * NH];   // swizzled k32 images
__device__ __align__(128) __nv_bfloat16 g_h1hi[2 * NH], g_h1lo[2 * NH];
__device__ __align__(128) float g_h1f[(size_t)T_STEPS * NH];              // fp32 h1 history for fc
__device__ __align__(128) float g_projP[VOCAB * G_DIM];                   // emb@W_ih0^T + b, unit-major
__device__ __align__(128) float g_b1U[G_DIM];
__device__ __align__(128) float g_c0[NH], g_c1[NH];
__device__ float g_acc[N_SEQ], g_len[N_SEQ];

// ---------------- helpers ----------------
__device__ __forceinline__ unsigned smem_u32(const void* p) {
    unsigned a;
    asm("{ .reg .u64 t; cvta.to.shared.u64 t, %1; cvt.u32.u64 %0, t; }" : "=r"(a) : "l"(p));
    return a;
}
// elem offset inside a 128x32 bf16 image, 64B rows, conflict-free ldmatrix swizzle
__device__ __forceinline__ int eoff32(int r, int kk) {
    return r * 32 + ((((kk >> 3) ^ ((r >> 1) & 3)) & 3) << 3) + (kk & 7);
}
__device__ __forceinline__ float fsig(float x) { return __fdividef(1.0f, 1.0f + __expf(-x)); }
__device__ __forceinline__ float ftanh(float x) { return __fdividef(2.0f, 1.0f + __expf(-2.0f * x)) - 1.0f; }

#define MBAR_INIT(addr, cnt) \
    asm volatile("mbarrier.init.shared.b64 [%0], %1;" :: "r"(addr), "r"(cnt) : "memory")
#define MBAR_EXPECT(addr, tx) \
    asm volatile("mbarrier.arrive.expect_tx.shared.b64 _, [%0], %1;" :: "r"(addr), "r"(tx) : "memory")
#define BULK_G2S(dst, src, bytes, mb) \
    asm volatile("cp.async.bulk.shared::cta.global.mbarrier::complete_tx::bytes [%0], [%1], %2, [%3];" \
                 :: "r"(dst), "l"(src), "r"(bytes), "r"(mb) : "memory")

__device__ __forceinline__ void mbar_wait(unsigned addr, unsigned parity) {
    unsigned done;
    asm volatile("{\n\t.reg .pred p;\n\t"
                 "mbarrier.try_wait.parity.acquire.cta.shared::cta.b64 p, [%1], %2;\n\t"
                 "selp.b32 %0, 1, 0, p;\n\t}" : "=r"(done) : "r"(addr), "r"(parity) : "memory");
    if (!done) {
        asm volatile("{\n\t.reg .pred P1;\n\t"
                     "WL_%=:\n\t"
                     "mbarrier.try_wait.parity.acquire.cta.shared::cta.b64 P1, [%0], %1, 0x989680;\n\t"
                     "@P1 bra.uni WD_%=;\n\t"
                     "bra.uni WL_%=;\n\t"
                     "WD_%=:\n\t}" :: "r"(addr), "r"(parity) : "memory");
    }
}

#define LDSM4(r0, r1, r2, r3, addr) \
    asm volatile("ldmatrix.sync.aligned.m8n8.x4.shared.b16 {%0,%1,%2,%3}, [%4];" \
                 : "=r"(r0), "=r"(r1), "=r"(r2), "=r"(r3) : "r"(addr))

#define MMA16816(d, a, b0, b1) \
    asm volatile("mma.sync.aligned.m16n8k16.row.col.f32.bf16.bf16.f32 " \
                 "{%0,%1,%2,%3}, {%4,%5,%6,%7}, {%8,%9}, {%0,%1,%2,%3};" \
                 : "+f"((d)[0]), "+f"((d)[1]), "+f"((d)[2]), "+f"((d)[3]) \
                 : "r"((a)[0]), "r"((a)[1]), "r"((a)[2]), "r"((a)[3]), "r"(b0), "r"(b1))

// ---------------- shared GEMM building blocks ----------------
// issue one k32 chunk's 4 bulk copies into stage at smem 'st', barrier 'mb'
__device__ __forceinline__ void issue_chunk(bool isL1, int t, int bM, int bN, int c,
                                            unsigned st, unsigned mb) {
    const __nv_bfloat16 *ah, *al, *wh, *wl;
    if (!isL1) {
        size_t o = (size_t)((t + 1) & 1) * NH + (size_t)(c * 32 + bM) * IMG_E;
        ah = g_h0hi + o; al = g_h0lo + o;
        wh = g_W0hi + (size_t)(bN * 8 + c) * IMG_E;
        wl = g_W0lo + (size_t)(bN * 8 + c) * IMG_E;
    } else if (c < 8) {
        size_t o = (size_t)(t & 1) * NH + (size_t)(c * 32 + bM) * IMG_E;
        ah = g_h0hi + o; al = g_h0lo + o;
        wh = g_W1hi + (size_t)(bN * 16 + c) * IMG_E;
        wl = g_W1lo + (size_t)(bN * 16 + c) * IMG_E;
    } else {
        size_t o = (size_t)((t + 1) & 1) * NH + (size_t)((c - 8) * 32 + bM) * IMG_E;
        ah = g_h1hi + o; al = g_h1lo + o;
        wh = g_W1hi + (size_t)(bN * 16 + c) * IMG_E;
        wl = g_W1lo + (size_t)(bN * 16 + c) * IMG_E;
    }
    MBAR_EXPECT(mb, (unsigned)STAGE_BYTES);
    BULK_G2S(st,          ah, (unsigned)IMG_B, mb);
    BULK_G2S(st + 8192u,  al, (unsigned)IMG_B, mb);
    BULK_G2S(st + 16384u, wh, (unsigned)IMG_B, mb);
    BULK_G2S(st + 24576u, wl, (unsigned)IMG_B, mb);
}

// one k32 chunk of split-3 bf16 HMMA into acc (16-warp layout: warp tile 32x32)
__device__ __forceinline__ void compute_chunk(unsigned stg, float acc[2][4][4],
                                              const unsigned offA[2], const unsigned rxA[2], unsigned khA,
                                              const unsigned offB[2], const unsigned rxB[2], unsigned khB) {
#pragma unroll
    for (int ks = 0; ks < 2; ks++) {
#pragma unroll
        for (int p = 0; p < 2; p++) {
            unsigned bd = stg + 16384u + offB[p] + ((((unsigned)(ks * 2) + khB) ^ rxB[p]) << 4);
            uint32_t bh[4], bl[4];
            LDSM4(bh[0], bh[1], bh[2], bh[3], bd);            // Bhi tiles 2p, 2p+1
            LDSM4(bl[0], bl[1], bl[2], bl[3], bd + 8192u);    // Blo
#pragma unroll
            for (int mi = 0; mi < 2; mi++) {
                unsigned ad = stg + offA[mi] + ((((unsigned)(ks * 2) + khA) ^ rxA[mi]) << 4);
                uint32_t ah[4], al[4];
                LDSM4(ah[0], ah[1], ah[2], ah[3], ad);
                LDSM4(al[0], al[1], al[2], al[3], ad + 8192u);
                MMA16816(acc[mi][2 * p],     ah, bh[0], bh[1]);
                MMA16816(acc[mi][2 * p + 1], ah, bh[2], bh[3]);
                MMA16816(acc[mi][2 * p],     ah, bl[0], bl[1]);
                MMA16816(acc[mi][2 * p + 1], ah, bl[2], bl[3]);
                MMA16816(acc[mi][2 * p],     al, bh[0], bh[1]);
                MMA16816(acc[mi][2 * p + 1], al, bh[2], bh[3]);
            }
        }
    }
}

// gates -> LSTM pointwise -> swizzled hi/lo h images (+ fp32 h1 history)
__device__ __forceinline__ void epilogue_job(bool isL1, int t, int bM, int bN,
                                             float acc[2][4][4], int wM, int wC, int lane,
                                             const int* tokS) {
    float* cst = isL1 ? g_c1 : g_c0;
    __nv_bfloat16* ohi = (isL1 ? g_h1hi : g_h0hi) + (size_t)(t & 1) * NH;
    __nv_bfloat16* olo = (isL1 ? g_h1lo : g_h0lo) + (size_t)(t & 1) * NH;
    const int gID = lane >> 2, a4 = lane & 3;
#pragma unroll
    for (int mi = 0; mi < 2; mi++) {
#pragma unroll
        for (int rs = 0; rs < 2; rs++) {
            const int rloc = wM * 32 + mi * 16 + gID + rs * 8;
            const int n = bM * 128 + rloc;
            const float* bias4 = isL1 ? g_b1U : (g_projP + (size_t)tokS[rloc] * G_DIM);
#pragma unroll
            for (int jp = 0; jp < 2; jp++) {
                const int un = bN * 32 + wC * 8 + a4 * 2 + jp;
                float4 bb = *(const float4*)&bias4[un * 4];
                float gi = acc[mi][2 * jp][rs * 2 + 0] + bb.x;
                float gf = acc[mi][2 * jp][rs * 2 + 1] + bb.y;
                float gg = acc[mi][2 * jp + 1][rs * 2 + 0] + bb.z;
                float go = acc[mi][2 * jp + 1][rs * 2 + 1] + bb.w;
                size_t ci = (size_t)n * H_DIM + un;
                float ii = fsig(gi), ff = fsig(gf), gv = ftanh(gg), oo = fsig(go);
                float cn = ff * cst[ci] + ii * gv;
                cst[ci] = cn;
                float h = oo * ftanh(cn);
                __nv_bfloat16 hh = __float2bfloat16(h);
                __nv_bfloat16 hl = __float2bfloat16(h - __bfloat162float(hh));
                int off = ((un >> 5) * 32 + bM) * IMG_E + eoff32(rloc, un & 31);
                ohi[off] = hh; olo[off] = hl;
                if (isL1) g_h1f[(size_t)t * NH + ci] = h;
            }
        }
    }
}

// ---------------- prep kernels ----------------
// permuted column for (gate, unit q), 16-warp epilogue-register-local mapping
__device__ __forceinline__ int perm_nloc(int gate, int q, int& blockN) {
    blockN = q >> 5;
    int rem = q & 31, wcol = rem >> 3, rem2 = rem & 7, a = rem2 >> 1, jp = rem2 & 1;
    return wcol * 32 + 16 * jp + 8 * (gate >> 1) + 2 * a + (gate & 1);
}

__global__ void prep_w(const float* __restrict__ W_hh0,
                       const float* __restrict__ W_ih1, const float* __restrict__ W_hh1,
                       const float* __restrict__ b_ih1, const float* __restrict__ b_hh1) {
    int jo = blockIdx.x, tid = threadIdx.x;          // original gate row 0..1023
    int gate = jo >> 8, q = jo & 255;
    int bN;
    int nloc = perm_nloc(gate, q, bN);
    for (int k = tid; k < H_DIM; k += 128) {         // W0 = W_hh0 only (ih0 folded into proj)
        float v = W_hh0[jo * H_DIM + k];
        __nv_bfloat16 hi = __float2bfloat16(v);
        __nv_bfloat16 lo = __float2bfloat16(v - __bfloat162float(hi));
        int idx = (bN * 8 + (k >> 5)) * IMG_E + eoff32(nloc, k & 31);
        g_W0hi[idx] = hi; g_W0lo[idx] = lo;
    }
    for (int k = tid; k < 512; k += 128) {           // W1 = [W_ih1 | W_hh1]
        float v = (k < H_DIM) ? W_ih1[jo * H_DIM + k] : W_hh1[jo * H_DIM + k - H_DIM];
        __nv_bfloat16 hi = __float2bfloat16(v);
        __nv_bfloat16 lo = __float2bfloat16(v - __bfloat162float(hi));
        int idx = (bN * 16 + (k >> 5)) * IMG_E + eoff32(nloc, k & 31);
        g_W1hi[idx] = hi; g_W1lo[idx] = lo;
    }
    if (tid == 0) g_b1U[q * 4 + gate] = b_ih1[jo] + b_hh1[jo];
}

__global__ void prep_proj(const float* __restrict__ emb, const float* __restrict__ W_ih0,
                          const float* __restrict__ b_ih0, const float* __restrict__ b_hh0) {
    __shared__ float e[E_DIM];
    int tok = blockIdx.x, tid = threadIdx.x;
    if (tid < E_DIM) e[tid] = emb[tok * E_DIM + tid];
    __syncthreads();
    for (int jo = tid; jo < G_DIM; jo += 256) {
        int gate = jo >> 8, q = jo & 255;
        float s = b_ih0[jo] + b_hh0[jo];
        for (int k = 0; k < E_DIM; k++) s += e[k] * W_ih0[jo * E_DIM + k];
        g_projP[tok * G_DIM + q * 4 + gate] = s;
    }
}

__global__ void init_kernel() {
    int i = blockIdx.x * 256 + threadIdx.x;          // NH threads
    __nv_bfloat16 z = __float2bfloat16(0.0f);
    g_h0hi[NH + i] = z; g_h0lo[NH + i] = z;          // buffer 1 = prev-state at t=0
    g_h1hi[NH + i] = z; g_h1lo[NH + i] = z;
    g_c0[i] = 0.0f; g_c1[i] = 0.0f;
    if (i < N_SEQ) g_acc[i] = 0.0f;
}

__global__ void len_kernel(const int* __restrict__ x) {
    int n = blockIdx.x * 8 + (threadIdx.x >> 5);
    int lane = threadIdx.x & 31;
    int cnt = 0;
    for (int j = lane; j < SEQ_S; j += 32) cnt += (x[n * SEQ_S + j] != 0);
    for (int o = 16; o; o >>= 1) cnt += __shfl_down_sync(0xffffffffu, cnt, o);
    if (lane == 0) g_len[n] = (float)cnt;
}

// ---------------- main: layer0 step tau + layer1 step tau-1, interleaved CTAs ----------------
// CTA tile M=128 x N=128, 16 warps (warp tile 32x32), split-3 bf16 HMMA, k32 chunks,
// 3-stage bulk-async pipeline, 2 CTAs/SM (32 warps/SM).
__global__ __launch_bounds__(NTHR, 2)
void lstm_mma(const int* __restrict__ x, int tau) {
    extern __shared__ char smraw[];
    const bool isL1 = (blockIdx.x & 1);
    if (!isL1 && tau >= T_STEPS) return;
    if (isL1 && tau == 0) return;
    const int t = isL1 ? tau - 1 : tau;
    const int cta = blockIdx.x >> 1;
    const int bM = cta >> 3, bN = cta & 7;
    const int NC = isL1 ? 16 : 8;

    unsigned base = smem_u32(smraw);
    unsigned sb = (base + 127u) & ~127u;
    unsigned mbB = sb + NSTAGE * STAGE_BYTES;
    int* tokS = (int*)(smraw + (sb - base) + NSTAGE * STAGE_BYTES + 128);

    const int tid = threadIdx.x;
    if (tid == 0) { MBAR_INIT(mbB + 0, 1); MBAR_INIT(mbB + 8, 1); MBAR_INIT(mbB + 16, 1); }
    if (!isL1 && tid < 128) tokS[tid] = x[(bM * 128 + tid) * SEQ_S + t];
    __syncthreads();

    if (tid == 0)
        for (int p = 0; p < NSTAGE && p < NC; p++)
            issue_chunk(isL1, t, bM, bN, p, sb + p * STAGE_BYTES, mbB + p * 8);

    // per-lane ldmatrix addressing (16-warp layout)
    const int wid = tid >> 5, lane = tid & 31;
    const int wM = wid & 3, wC = wid >> 2;            // wM 0..3, wC 0..3
    const int rowm = (lane & 7) + ((lane >> 3) & 1) * 8;
    const unsigned khA = (unsigned)(lane >> 4);
    unsigned offA[2], rxA[2];
#pragma unroll
    for (int mi = 0; mi < 2; mi++) {
        int r = wM * 32 + mi * 16 + rowm;
        offA[mi] = r * 64; rxA[mi] = (r >> 1) & 3;
    }
    const unsigned khB = (unsigned)((lane >> 3) & 1);
    unsigned offB[2], rxB[2];
#pragma unroll
    for (int p = 0; p < 2; p++) {
        int n = wC * 32 + (2 * p + ((lane >> 4) & 1)) * 8 + (lane & 7);
        offB[p] = n * 64; rxB[p] = (n >> 1) & 3;
    }

    float acc[2][4][4];
#pragma unroll
    for (int mi = 0; mi < 2; mi++)
#pragma unroll
        for (int j = 0; j < 4; j++)
#pragma unroll
            for (int r = 0; r < 4; r++) acc[mi][j][r] = 0.0f;

    for (int c = 0; c < NC; c++) {
        const int s = c % NSTAGE;
        mbar_wait(mbB + s * 8, (unsigned)((c / NSTAGE) & 1));
        compute_chunk(sb + s * STAGE_BYTES, acc, offA, rxA, khA, offB, rxB, khB);
        __syncthreads();
        if (tid == 0 && c + NSTAGE < NC)
            issue_chunk(isL1, t, bM, bN, c + NSTAGE, sb + s * STAGE_BYTES, mbB + s * 8);
    }
    epilogue_job(isL1, t, bM, bN, acc, wM, wC, lane, tokS);
}

// ---------------- fc + relu + log_softmax + probs + masked NLL ----------------
__global__ __launch_bounds__(288)
void fc_kernel(const float* __restrict__ fc_W, const float* __restrict__ fc_b,
               const int* __restrict__ x, float* __restrict__ out) {
    __shared__ float Ws[VOCAB][H_DIM + 1];
    __shared__ float hs[8][H_DIM];
    __shared__ float lg[8][VOCAB + 2];
    __shared__ float lse_s[8];

    const int t = blockIdx.y;
    const int n0 = blockIdx.x * 8;
    const int tid = threadIdx.x;

    for (int i = tid; i < VOCAB * H_DIM; i += 288) Ws[i / H_DIM][i % H_DIM] = fc_W[i];
    const float* hsrc = g_h1f + (size_t)t * NH + (size_t)n0 * H_DIM;
    for (int i = tid; i < 8 * H_DIM; i += 288) hs[i / H_DIM][i % H_DIM] = hsrc[i];
    __syncthreads();

    int s = tid / VOCAB;
    int v = tid - s * VOCAB;
    float a = fc_b[v];
#pragma unroll 8
    for (int k = 0; k < H_DIM; k++) a += hs[s][k] * Ws[v][k];
    float l = fmaxf(a, 0.0f);
    lg[s][v] = l;
    __syncthreads();

    if (v == 0) {
        float m = -1e30f;
        for (int j = 0; j < VOCAB; j++) m = fmaxf(m, lg[s][j]);
        float sum = 0.0f;
        for (int j = 0; j < VOCAB; j++) sum += expf(lg[s][j] - m);
        lse_s[s] = m + logf(sum);
    }
    __syncthreads();

    float lse = lse_s[s];
    int n = n0 + s;
    out[((size_t)n * T_STEPS + t) * VOCAB + v] = expf(l - lse);
    int tgt = x[n * SEQ_S + t + 1];
    if (v == tgt && tgt != 0) atomicAdd(&g_acc[n], lse - l);
}

__global__ void finalize_kernel(float* __restrict__ out) {
    __shared__ float red[1024];
    int tid = threadIdx.x;
    float sum = 0.0f;
    for (int n = tid; n < N_SEQ; n += 1024) {
        float ml = g_acc[n] / g_len[n];
        out[PROBS_OFF + n] = ml;
        sum += ml;
    }
    red[tid] = sum;
    __syncthreads();
    for (int sft = 512; sft > 0; sft >>= 1) {
        if (tid < sft) red[tid] += red[tid + sft];
        __syncthreads();
    }
    if (tid == 0) out[PROBS_OFF + N_SEQ] = red[0] / (float)N_SEQ;
}

// ---------------- launch (lstm_mma tau=2 sits at ncu sample index 5) ----------------
extern "C" void kernel_launch(void* const* d_in, const int* in_sizes, int n_in,
                              void* d_out, int out_size) {
    const int*   x     = (const int*)  d_in[0];
    const float* emb   = (const float*)d_in[1];
    const float* W_ih0 = (const float*)d_in[2];
    const float* W_hh0 = (const float*)d_in[3];
    const float* b_ih0 = (const float*)d_in[4];
    const float* b_hh0 = (const float*)d_in[5];
    const float* W_ih1 = (const float*)d_in[6];
    const float* W_hh1 = (const float*)d_in[7];
    const float* b_ih1 = (const float*)d_in[8];
    const float* b_hh1 = (const float*)d_in[9];
    const float* fc_W  = (const float*)d_in[10];
    const float* fc_b  = (const float*)d_in[11];
    float* out = (float*)d_out;

    cudaFuncSetAttribute(lstm_mma, cudaFuncAttributeMaxDynamicSharedMemorySize, SMEM_SZ);

    init_kernel<<<NH / 256, 256>>>();                                    // launch 0
    prep_proj<<<VOCAB, 256>>>(emb, W_ih0, b_ih0, b_hh0);                 // launch 1
    prep_w<<<G_DIM, 128>>>(W_hh0, W_ih1, W_hh1, b_ih1, b_hh1);           // launch 2

    for (int tau = 0; tau <= T_STEPS; tau++)                             // launches 3..130
        lstm_mma<<<512, NTHR, SMEM_SZ>>>(x, tau);

    len_kernel<<<N_SEQ / 8, 256>>>(x);
    fc_kernel<<<dim3(N_SEQ / 8, T_STEPS), 288>>>(fc_W, fc_b, x, out);
    finalize_kernel<<<1, 1024>>>(out);
}